// round 15
// baseline (speedup 1.0000x reference)
#include <cuda_runtime.h>
#include <cuda_bf16.h>
#include <math.h>
#include <stdint.h>
typedef unsigned short u16;

#define Tn 2048
#define Hn 2048
#define NHn 16
#define NKVn 4
#define HDn 128
#define En 8
#define Fn 4096
#define FSn 4096
#define QD (NHn*HDn)
#define KD (NKVn*HDn)

// ---------- fp32 scratch ----------
__device__ float g_x1[Tn*Hn];
__device__ float g_q[Tn*QD];
__device__ float g_k[Tn*KD];
__device__ float g_v[Tn*KD];
__device__ float g_attn[Tn*QD];
__device__ float g_hidden[Tn*Hn];
__device__ float g_x2[Tn*Hn];
__device__ float g_gbuf[2*Tn*Fn];
__device__ float g_ubuf[2*Tn*Fn];
__device__ float g_moe[2*Tn*Hn];
__device__ float g_sgg[Tn*FSn];
__device__ float g_sgu[Tn*FSn];
__device__ float g_so[Tn*Hn];
__device__ float g_sgate[Tn];
__device__ int   g_te[Tn*2];
__device__ float g_tw[Tn*2];
__device__ int   g_ptok[2*Tn];
__device__ int   g_pslot[2*Tn];
__device__ float g_pw[2*Tn];
__device__ int   g_cnt[En];
__device__ int   g_off[En];

// ---------- bf16 hi/lo planes (weights transposed to [N][K]) ----------
__device__ u16 g_wqh[Hn*QD],  g_wql[Hn*QD];
__device__ u16 g_wkh[Hn*KD],  g_wkl[Hn*KD];
__device__ u16 g_wvh[Hn*KD],  g_wvl[Hn*KD];
__device__ u16 g_woh[QD*Hn],  g_wol[QD*Hn];
__device__ u16 g_wgh[(size_t)En*Hn*Fn], g_wgl[(size_t)En*Hn*Fn];
__device__ u16 g_wuh[(size_t)En*Hn*Fn], g_wul[(size_t)En*Hn*Fn];
__device__ u16 g_wdh[(size_t)En*Fn*Hn], g_wdl[(size_t)En*Fn*Hn];
__device__ u16 g_wsgth[Hn*FSn], g_wsgtl[Hn*FSn];
__device__ u16 g_wsuph[Hn*FSn], g_wsupl[Hn*FSn];
__device__ u16 g_wsdnh[FSn*Hn], g_wsdnl[FSn*Hn];
__device__ u16 g_x1h[Tn*Hn],  g_x1l[Tn*Hn];
__device__ u16 g_ath[Tn*QD],  g_atl[Tn*QD];
__device__ u16 g_x2h[Tn*Hn],  g_x2l[Tn*Hn];
__device__ u16 g_acth[2*Tn*Fn], g_actl[2*Tn*Fn];
__device__ u16 g_sacth[Tn*FSn], g_sactl[Tn*FSn];

// ---------- helpers ----------
__device__ __forceinline__ uint32_t smem_u32(const void* p){
    uint32_t a; asm("{ .reg .u64 t; cvta.to.shared.u64 t, %1; cvt.u32.u64 %0, t; }":"=r"(a):"l"(p)); return a;
}
__device__ __forceinline__ void cpa16(uint32_t dst, const void* src){
    asm volatile("cp.async.cg.shared.global [%0], [%1], 16;" :: "r"(dst), "l"(src) : "memory");
}
template<int N> __device__ __forceinline__ void cp_wait(){
    asm volatile("cp.async.wait_group %0;" :: "n"(N) : "memory");
}
__device__ __forceinline__ void ldsm4(uint32_t* r, uint32_t a){
    asm volatile("ldmatrix.sync.aligned.m8n8.x4.shared.b16 {%0,%1,%2,%3}, [%4];"
        : "=r"(r[0]),"=r"(r[1]),"=r"(r[2]),"=r"(r[3]) : "r"(a));
}
__device__ __forceinline__ void mma16816(float* c, const uint32_t* a, uint32_t b0, uint32_t b1){
    asm volatile("mma.sync.aligned.m16n8k16.row.col.f32.bf16.bf16.f32 "
        "{%0,%1,%2,%3}, {%4,%5,%6,%7}, {%8,%9}, {%0,%1,%2,%3};"
        : "+f"(c[0]),"+f"(c[1]),"+f"(c[2]),"+f"(c[3])
        : "r"(a[0]),"r"(a[1]),"r"(a[2]),"r"(a[3]),"r"(b0),"r"(b1));
}

// smem layout: 4 planes of 128 rows x 32 bf16, row stride 80B (conflict-free ldmatrix)
#define RSB    80
#define PLANE  (128*RSB)       // 10240
#define OF_AL  PLANE
#define OF_BH  (2*PLANE)
#define OF_BL  (3*PLANE)
#define STAGE  (4*PLANE)       // 40960
#define GEMM_SMEM (2*STAGE)    // 81920

// ---------- converters ----------
__global__ void __launch_bounds__(256) transpose_split_kernel(
    const float* __restrict__ W, u16* __restrict__ Th, u16* __restrict__ Tl, int K, int N)
{
    __shared__ float tile[32][33];
    size_t zo = (size_t)blockIdx.z * K * N;
    W += zo; Th += zo; Tl += zo;
    int nt = blockIdx.x*32, kt = blockIdx.y*32;
    int tx = threadIdx.x & 31, ty = threadIdx.x >> 5;
#pragma unroll
    for (int j = 0; j < 32; j += 8) tile[ty+j][tx] = W[(size_t)(kt+ty+j)*N + nt + tx];
    __syncthreads();
#pragma unroll
    for (int j = 0; j < 32; j += 8) {
        float v = tile[tx][ty+j];
        __nv_bfloat16 hb = __float2bfloat16(v);
        size_t o = (size_t)(nt+ty+j)*K + kt + tx;
        Th[o] = __bfloat16_as_ushort(hb);
        Tl[o] = __bfloat16_as_ushort(__float2bfloat16(v - __bfloat162float(hb)));
    }
}
__global__ void split_kernel(const float* __restrict__ x, u16* __restrict__ h, u16* __restrict__ l, int n)
{
    int i = blockIdx.x*blockDim.x + threadIdx.x;
    for (; i < n; i += gridDim.x*blockDim.x) {
        float v = x[i];
        __nv_bfloat16 hb = __float2bfloat16(v);
        h[i] = __bfloat16_as_ushort(hb);
        l[i] = __bfloat16_as_ushort(__float2bfloat16(v - __bfloat162float(hb)));
    }
}
__global__ void silumul_split_kernel(const float* __restrict__ g, const float* __restrict__ u,
                                     u16* __restrict__ h, u16* __restrict__ l, int n)
{
    int i = blockIdx.x*blockDim.x + threadIdx.x;
    for (; i < n; i += gridDim.x*blockDim.x) {
        float gv = g[i];
        float v = gv/(1.f+__expf(-gv))*u[i];
        __nv_bfloat16 hb = __float2bfloat16(v);
        h[i] = __bfloat16_as_ushort(hb);
        l[i] = __bfloat16_as_ushort(__float2bfloat16(v - __bfloat162float(hb)));
    }
}

// ---------- split-bf16 HMMA GEMM ----------
// C = A@B^T, B planes [N][K]. 128x128 tile, BK=32, 8 warps (4m x 2n), warp tile 32x64.
// MODE: 0 plain, 1 +Cadd, 2 gather A rows via g_ptok -> contiguous C, 3 contiguous A -> scatter*weight to g_moe
template<int MODE>
__global__ void __launch_bounds__(256, 2) gemm_mma(
    const u16* __restrict__ Ah_, const u16* __restrict__ Al_,
    const u16* __restrict__ Bh_, const u16* __restrict__ Bl_,
    const float* __restrict__ Cadd, float* __restrict__ C,
    int M, int N, int K)
{
    int cnt = M, off = 0;
    const u16 *Bh = Bh_, *Bl = Bl_;
    if (MODE >= 2) {
        int e = blockIdx.z;
        cnt = g_cnt[e]; off = g_off[e];
        size_t bo = (size_t)e * K * N;
        Bh += bo; Bl += bo;
    }
    const int bm = blockIdx.y * 128;
    if (bm >= cnt) return;
    const int bn = blockIdx.x * 128;

    extern __shared__ char smc[];
    const uint32_t sb = smem_u32(smc);
    const int tid = threadIdx.x, wid = tid>>5, lane = tid&31;

    // ---- gmem load mapping ----
    const int ar = tid >> 1, half = tid & 1;
    int grow;
    if (MODE == 2)      { int r = bm+ar; if (r >= cnt) r = cnt-1; grow = g_ptok[off + r]; }
    else if (MODE == 3) { int r = bm+ar; if (r >= cnt) r = cnt-1; grow = off + r; }
    else                  grow = bm + ar;
    const u16* sAh = Ah_ + (size_t)grow*K + half*16;
    const u16* sAl = Al_ + (size_t)grow*K + half*16;
    const u16* sBh = Bh  + (size_t)(bn+ar)*K + half*16;
    const u16* sBl = Bl  + (size_t)(bn+ar)*K + half*16;
    const uint32_t dA = sb + ar*RSB + half*32;

    // ---- compute-side smem addresses ----
    const int wm = wid & 3, wn = wid >> 2;
    // A: x4 ldmatrix, lanes 0-15 rows, lanes>=16 -> +16B col
    const uint32_t aBase = sb + (uint32_t)(wm*32 + (lane & 15))*RSB + (uint32_t)(lane >> 4)*16;
    // B: x4 ldmatrix over a PAIR of n-tiles: m=lane>>3: row += (m>>1)*8, col += (m&1)*16
    const uint32_t bBase = sb + OF_BH
        + (uint32_t)(wn*64 + (lane & 7) + ((lane >> 4) & 1)*8)*RSB
        + (uint32_t)((lane >> 3) & 1)*16;

    float acc[2][8][4];
#pragma unroll
    for (int mt = 0; mt < 2; mt++)
#pragma unroll
        for (int nt = 0; nt < 8; nt++)
#pragma unroll
            for (int j = 0; j < 4; j++) acc[mt][nt][j] = 0.f;

    const int ktiles = K / 32;

#define ISSUE(st, kb) do { \
    uint32_t d_ = dA + (uint32_t)(st)*STAGE; const int ko_ = (kb)*32; \
    cpa16(d_,            sAh + ko_); cpa16(d_ + 16,            sAh + ko_ + 8); \
    cpa16(d_ + OF_AL,    sAl + ko_); cpa16(d_ + OF_AL + 16,    sAl + ko_ + 8); \
    cpa16(d_ + OF_BH,    sBh + ko_); cpa16(d_ + OF_BH + 16,    sBh + ko_ + 8); \
    cpa16(d_ + OF_BL,    sBl + ko_); cpa16(d_ + OF_BL + 16,    sBl + ko_ + 8); \
    asm volatile("cp.async.commit_group;" ::: "memory"); } while(0)

    ISSUE(0, 0);
    for (int kb = 0; kb < ktiles; kb++) {
        cp_wait<0>();
        __syncthreads();
        if (kb + 1 < ktiles) ISSUE((kb+1)&1, kb+1);   // overlaps with compute below
        const uint32_t st = (uint32_t)(kb & 1) * STAGE;
#pragma unroll
        for (int ks = 0; ks < 2; ks++) {
            // A fragments (hi + lo), both m-tiles
            uint32_t ah[2][4], al[2][4];
#pragma unroll
            for (int mt = 0; mt < 2; mt++) {
                uint32_t aa = aBase + st + (uint32_t)mt*16*RSB + (uint32_t)ks*32;
                ldsm4(ah[mt], aa);
                ldsm4(al[mt], aa + OF_AL);
            }
#pragma unroll
            for (int ng = 0; ng < 2; ng++) {
                // B fragments for 4 n-tiles via paired x4 ldmatrix
                uint32_t bh[8], bl[8];
                uint32_t b0 = bBase + st + (uint32_t)(ng*32)*RSB + (uint32_t)ks*32;
                uint32_t b1 = b0 + 16*RSB;
                ldsm4(&bh[0], b0);           // nt = 4ng+0, 4ng+1
                ldsm4(&bh[4], b1);           // nt = 4ng+2, 4ng+3
                ldsm4(&bl[0], b0 + PLANE);
                ldsm4(&bl[4], b1 + PLANE);
                // term-major: 8 independent accumulators between reuses
#pragma unroll
                for (int q = 0; q < 4; q++)
#pragma unroll
                    for (int mt = 0; mt < 2; mt++)
                        mma16816(acc[mt][ng*4+q], ah[mt], bh[2*q], bh[2*q+1]);
#pragma unroll
                for (int q = 0; q < 4; q++)
#pragma unroll
                    for (int mt = 0; mt < 2; mt++)
                        mma16816(acc[mt][ng*4+q], ah[mt], bl[2*q], bl[2*q+1]);
#pragma unroll
                for (int q = 0; q < 4; q++)
#pragma unroll
                    for (int mt = 0; mt < 2; mt++)
                        mma16816(acc[mt][ng*4+q], al[mt], bh[2*q], bh[2*q+1]);
            }
        }
    }
#undef ISSUE

    // ---- epilogue ----
    const int gid = lane >> 2, tg = lane & 3;
    const int cb = bn + wn*64 + tg*2;
#pragma unroll
    for (int mt = 0; mt < 2; mt++) {
        const int lr0 = wm*32 + mt*16 + gid;
        const int lr1 = lr0 + 8;
        if (MODE == 3) {
            const bool v0 = (bm + lr0) < cnt, v1 = (bm + lr1) < cnt;
            int p0 = off + bm + lr0, p1 = off + bm + lr1;
            int tok0 = v0 ? g_ptok[p0] : 0, slot0 = v0 ? g_pslot[p0] : 0;
            int tok1 = v1 ? g_ptok[p1] : 0, slot1 = v1 ? g_pslot[p1] : 0;
            float w0 = v0 ? g_pw[p0] : 0.f, w1 = v1 ? g_pw[p1] : 0.f;
            float* d0 = g_moe + (size_t)slot0*Tn*Hn + (size_t)tok0*Hn + cb;
            float* d1 = g_moe + (size_t)slot1*Tn*Hn + (size_t)tok1*Hn + cb;
#pragma unroll
            for (int nt = 0; nt < 8; nt++) {
                if (v0) { float2 o; o.x = acc[mt][nt][0]*w0; o.y = acc[mt][nt][1]*w0; *(float2*)(d0 + nt*8) = o; }
                if (v1) { float2 o; o.x = acc[mt][nt][2]*w1; o.y = acc[mt][nt][3]*w1; *(float2*)(d1 + nt*8) = o; }
            }
        } else if (MODE == 2) {
            const bool v0 = (bm + lr0) < cnt, v1 = (bm + lr1) < cnt;
            float* d0 = C + (size_t)(off + bm + lr0)*N + cb;
            float* d1 = C + (size_t)(off + bm + lr1)*N + cb;
#pragma unroll
            for (int nt = 0; nt < 8; nt++) {
                if (v0) { float2 o; o.x = acc[mt][nt][0]; o.y = acc[mt][nt][1]; *(float2*)(d0 + nt*8) = o; }
                if (v1) { float2 o; o.x = acc[mt][nt][2]; o.y = acc[mt][nt][3]; *(float2*)(d1 + nt*8) = o; }
            }
        } else {
            float* d0 = C + (size_t)(bm + lr0)*N + cb;
            float* d1 = C + (size_t)(bm + lr1)*N + cb;
            if (MODE == 1) {
                const float* a0 = Cadd + (size_t)(bm + lr0)*N + cb;
                const float* a1 = Cadd + (size_t)(bm + lr1)*N + cb;
#pragma unroll
                for (int nt = 0; nt < 8; nt++) {
                    float2 r0 = *(const float2*)(a0 + nt*8);
                    float2 r1 = *(const float2*)(a1 + nt*8);
                    float2 o0; o0.x = acc[mt][nt][0] + r0.x; o0.y = acc[mt][nt][1] + r0.y;
                    float2 o1; o1.x = acc[mt][nt][2] + r1.x; o1.y = acc[mt][nt][3] + r1.y;
                    *(float2*)(d0 + nt*8) = o0;
                    *(float2*)(d1 + nt*8) = o1;
                }
            } else {
#pragma unroll
                for (int nt = 0; nt < 8; nt++) {
                    float2 o0; o0.x = acc[mt][nt][0]; o0.y = acc[mt][nt][1];
                    float2 o1; o1.x = acc[mt][nt][2]; o1.y = acc[mt][nt][3];
                    *(float2*)(d0 + nt*8) = o0;
                    *(float2*)(d1 + nt*8) = o1;
                }
            }
        }
    }
}

// ---------- non-GEMM kernels (unchanged, passing) ----------
__global__ void __launch_bounds__(256) rmsnorm_kernel(
    const float* __restrict__ x, const float* __restrict__ w, float* __restrict__ y)
{
    int t = blockIdx.x, tid = threadIdx.x;
    __shared__ float red[256]; __shared__ float rs;
    const float* xr = x + (size_t)t*Hn;
    float s = 0.f;
    for (int j = tid; j < Hn; j += 256) { float v = xr[j]; s += v*v; }
    red[tid] = s; __syncthreads();
    for (int o = 128; o > 0; o >>= 1) { if (tid < o) red[tid] += red[tid+o]; __syncthreads(); }
    if (tid == 0) rs = rsqrtf(red[0]/(float)Hn + 1e-6f);
    __syncthreads();
    float* yr = y + (size_t)t*Hn;
    for (int j = tid; j < Hn; j += 256) yr[j] = xr[j]*rs*w[j];
}

__global__ void rope_kernel(float* __restrict__ x, const int* __restrict__ pos, int nheads)
{
    int t = blockIdx.x, h = blockIdx.y, i = threadIdx.x;
    float* p = x + ((size_t)t*nheads + h)*HDn;
    float inv = powf(1.0e6f, -((float)i)/64.0f);
    float ang = (float)pos[t] * inv;
    float sv, cv; sincosf(ang, &sv, &cv);
    float a = p[i], b = p[i+64];
    p[i] = a*cv - b*sv;  p[i+64] = b*cv + a*sv;
}

#define ATTN_SMEM_BYTES ((64*132*2 + 64*65 + 192) * 4)
__global__ void __launch_bounds__(256) attn_kernel(
    const float* __restrict__ q, const float* __restrict__ k,
    const float* __restrict__ v, float* __restrict__ out)
{
    extern __shared__ float sm[];
    float* Qs  = sm;
    float* KVs = sm + 64*132;
    float* Ps  = sm + 2*64*132;
    float* m_s = Ps + 64*65;
    float* l_s = m_s + 64;
    float* al_s = l_s + 64;
    const int tid = threadIdx.x;
    const int m0 = blockIdx.x * 64;
    const int h  = blockIdx.y;
    const int kvh = h / (NHn/NKVn);
    const float scale = 0.08838834764831845f;
    {
        int r = tid >> 2, c = (tid & 3) * 32;
        const float* src = q + ((size_t)(m0 + r)*NHn + h)*HDn + c;
        float* dst = Qs + r*132 + c;
#pragma unroll
        for (int j = 0; j < 32; j += 4) *(float4*)(dst + j) = *(const float4*)(src + j);
    }
    if (tid < 64) { m_s[tid] = -INFINITY; l_s[tid] = 0.f; }
    const int tx = tid & 15, ty = tid >> 4;
    const int r0 = ty*4, sc0 = tx*4, oc0 = tx*8;
    float acc[4][8];
#pragma unroll
    for (int i = 0; i < 4; i++)
#pragma unroll
        for (int j = 0; j < 8; j++) acc[i][j] = 0.f;
    const int ntiles = m0/64 + 1;
    for (int t = 0; t < ntiles; ++t) {
        const int s0 = t*64;
        __syncthreads();
        {
            int r = tid >> 2, c = (tid & 3)*32;
            const float* src = k + ((size_t)(s0 + r)*NKVn + kvh)*HDn + c;
            float* dst = KVs + r*132 + c;
#pragma unroll
            for (int j = 0; j < 32; j += 4) *(float4*)(dst + j) = *(const float4*)(src + j);
        }
        __syncthreads();
        float s4[4][4];
#pragma unroll
        for (int i = 0; i < 4; i++)
#pragma unroll
            for (int j = 0; j < 4; j++) s4[i][j] = 0.f;
#pragma unroll 4
        for (int kk = 0; kk < HDn; kk += 4) {
            float4 a[4], b[4];
#pragma unroll
            for (int i = 0; i < 4; i++) a[i] = *(const float4*)(Qs + (r0+i)*132 + kk);
#pragma unroll
            for (int j = 0; j < 4; j++) b[j] = *(const float4*)(KVs + (sc0+j)*132 + kk);
#pragma unroll
            for (int i = 0; i < 4; i++)
#pragma unroll
                for (int j = 0; j < 4; j++)
                    s4[i][j] += a[i].x*b[j].x + a[i].y*b[j].y + a[i].z*b[j].z + a[i].w*b[j].w;
        }
#pragma unroll
        for (int i = 0; i < 4; i++)
#pragma unroll
            for (int j = 0; j < 4; j++) {
                float vv = s4[i][j]*scale;
                if (s0 + sc0 + j > m0 + r0 + i) vv = -1e30f;
                Ps[(r0+i)*65 + sc0 + j] = vv;
            }
        __syncthreads();
        {
            int r = tid >> 2, sub = tid & 3;
            float* prow = Ps + r*65 + sub*16;
            float mx = -INFINITY;
#pragma unroll
            for (int j2 = 0; j2 < 16; j2++) mx = fmaxf(mx, prow[j2]);
#pragma unroll
            for (int o = 1; o < 4; o <<= 1) mx = fmaxf(mx, __shfl_xor_sync(0xffffffffu, mx, o));
            float mprev = m_s[r];
            float mnew  = fmaxf(mprev, mx);
            float sum = 0.f;
#pragma unroll
            for (int j2 = 0; j2 < 16; j2++) { float p = __expf(prow[j2]-mnew); prow[j2] = p; sum += p; }
#pragma unroll
            for (int o = 1; o < 4; o <<= 1) sum += __shfl_xor_sync(0xffffffffu, sum, o);
            if (sub == 0) {
                float al = __expf(mprev - mnew);
                al_s[r] = al;  l_s[r] = l_s[r]*al + sum;  m_s[r] = mnew;
            }
        }
        __syncthreads();
        {
            int r = tid >> 2, c = (tid & 3)*32;
            const float* src = v + ((size_t)(s0 + r)*NKVn + kvh)*HDn + c;
            float* dst = KVs + r*132 + c;
#pragma unroll
            for (int j = 0; j < 32; j += 4) *(float4*)(dst + j) = *(const float4*)(src + j);
        }
        __syncthreads();
        {
#pragma unroll
            for (int i = 0; i < 4; i++) {
                float al = al_s[r0+i];
#pragma unroll
                for (int j = 0; j < 8; j++) acc[i][j] *= al;
            }
#pragma unroll 4
            for (int s = 0; s < 64; s++) {
                float4 v0 = *(const float4*)(KVs + s*132 + oc0);
                float4 v1 = *(const float4*)(KVs + s*132 + oc0 + 4);
                float p[4];
#pragma unroll
                for (int i = 0; i < 4; i++) p[i] = Ps[(r0+i)*65 + s];
#pragma unroll
                for (int i = 0; i < 4; i++) {
                    acc[i][0]=fmaf(p[i],v0.x,acc[i][0]); acc[i][1]=fmaf(p[i],v0.y,acc[i][1]);
                    acc[i][2]=fmaf(p[i],v0.z,acc[i][2]); acc[i][3]=fmaf(p[i],v0.w,acc[i][3]);
                    acc[i][4]=fmaf(p[i],v1.x,acc[i][4]); acc[i][5]=fmaf(p[i],v1.y,acc[i][5]);
                    acc[i][6]=fmaf(p[i],v1.z,acc[i][6]); acc[i][7]=fmaf(p[i],v1.w,acc[i][7]);
                }
            }
        }
    }
    __syncthreads();
#pragma unroll
    for (int i = 0; i < 4; i++) {
        float inv = 1.f / l_s[r0+i];
        float* dst = out + ((size_t)(m0 + r0 + i)*NHn + h)*HDn + oc0;
#pragma unroll
        for (int j = 0; j < 8; j++) dst[j] = acc[i][j]*inv;
    }
}

__global__ void __launch_bounds__(256) router_kernel(
    const float* __restrict__ x, const float* __restrict__ rw)
{
    int t = blockIdx.x;
    int w = threadIdx.x >> 5, lane = threadIdx.x & 31;
    __shared__ float lg[En];
    const float* xr = x + (size_t)t*Hn;
    float s = 0.f;
    for (int j = lane; j < Hn; j += 32) s += xr[j]*rw[(size_t)j*En + w];
#pragma unroll
    for (int o = 16; o > 0; o >>= 1) s += __shfl_xor_sync(0xffffffffu, s, o);
    if (lane == 0) lg[w] = s;
    __syncthreads();
    if (threadIdx.x == 0) {
        float mx = lg[0];
        for (int e = 1; e < En; e++) mx = fmaxf(mx, lg[e]);
        float p[En]; float sum = 0.f;
        for (int e = 0; e < En; e++) { p[e] = expf(lg[e]-mx); sum += p[e]; }
        for (int e = 0; e < En; e++) p[e] /= sum;
        int e0 = 0;
        for (int e = 1; e < En; e++) if (p[e] > p[e0]) e0 = e;
        int e1 = (e0 == 0) ? 1 : 0;
        for (int e = 0; e < En; e++) if (e != e0 && p[e] > p[e1]) e1 = e;
        float inv = 1.f/(p[e0]+p[e1]);
        g_te[t*2] = e0; g_te[t*2+1] = e1;
        g_tw[t*2] = p[e0]*inv; g_tw[t*2+1] = p[e1]*inv;
    }
}

__global__ void __launch_bounds__(128) sgate_kernel(
    const float* __restrict__ x, const float* __restrict__ wsg)
{
    int t = blockIdx.x, tid = threadIdx.x;
    __shared__ float red[128];
    const float* xr = x + (size_t)t*Hn;
    float s = 0.f;
    for (int j = tid; j < Hn; j += 128) s += xr[j]*wsg[j];
    red[tid] = s; __syncthreads();
    for (int o = 64; o > 0; o >>= 1) { if (tid < o) red[tid] += red[tid+o]; __syncthreads(); }
    if (tid == 0) g_sgate[t] = 1.f/(1.f + expf(-red[0]));
}

__global__ void __launch_bounds__(256) build_perm_kernel()
{
    __shared__ int cnt_s[En], off_s[En], cur[En];
    int tid = threadIdx.x;
    if (tid < En) cnt_s[tid] = 0;
    __syncthreads();
    for (int t = tid; t < Tn; t += 256) {
        atomicAdd(&cnt_s[g_te[t*2]], 1);
        atomicAdd(&cnt_s[g_te[t*2+1]], 1);
    }
    __syncthreads();
    if (tid == 0) { int o = 0; for (int e = 0; e < En; e++) { off_s[e] = o; o += cnt_s[e]; } }
    __syncthreads();
    if (tid < En) cur[tid] = off_s[tid];
    __syncthreads();
    for (int t = tid; t < Tn; t += 256) {
        for (int s = 0; s < 2; s++) {
            int e = g_te[t*2+s];
            int p = atomicAdd(&cur[e], 1);
            g_ptok[p] = t; g_pslot[p] = s; g_pw[p] = g_tw[t*2+s];
        }
    }
    __syncthreads();
    if (tid < En) { g_cnt[tid] = cnt_s[tid]; g_off[tid] = off_s[tid]; }
}

__global__ void combine_kernel(const float* __restrict__ hidden, const float* __restrict__ so,
                               float* __restrict__ out)
{
    const int total = Tn*Hn;
    int i = blockIdx.x*blockDim.x + threadIdx.x;
    for (; i < total; i += gridDim.x*blockDim.x) {
        int t = i / Hn;
        out[i] = hidden[i] + g_moe[i] + g_moe[total + i] + g_sgate[t]*so[i];
    }
}

// ---------- launch ----------
#define SYM(p, s) cudaGetSymbolAddress((void**)&p, s)
extern "C" void kernel_launch(void* const* d_in, const int* in_sizes, int n_in,
                              void* d_out, int out_size)
{
    (void)in_sizes; (void)n_in; (void)out_size;
    const float* hs   = (const float*)d_in[0];
    const int*   pos  = (const int*)  d_in[1];
    const float* ln1  = (const float*)d_in[2];
    const float* ln2  = (const float*)d_in[3];
    const float* wq   = (const float*)d_in[4];
    const float* wk   = (const float*)d_in[5];
    const float* wv   = (const float*)d_in[6];
    const float* wo   = (const float*)d_in[7];
    const float* rw   = (const float*)d_in[8];
    const float* wg   = (const float*)d_in[9];
    const float* wu   = (const float*)d_in[10];
    const float* wd   = (const float*)d_in[11];
    const float* wsgt = (const float*)d_in[12];
    const float* wsup = (const float*)d_in[13];
    const float* wsdn = (const float*)d_in[14];
    const float* wsg  = (const float*)d_in[15];
    float* out = (float*)d_out;

    float *x1p,*qp,*kp,*vp,*atp,*hidp,*x2p,*gbufp,*ubufp,*sggp,*sgup,*sop;
    SYM(x1p,g_x1); SYM(qp,g_q); SYM(kp,g_k); SYM(vp,g_v); SYM(atp,g_attn);
    SYM(hidp,g_hidden); SYM(x2p,g_x2); SYM(gbufp,g_gbuf); SYM(ubufp,g_ubuf);
    SYM(sggp,g_sgg); SYM(sgup,g_sgu); SYM(sop,g_so);

    u16 *wqh,*wql,*wkh,*wkl,*wvh,*wvl,*woh,*wol,*wgh,*wgl,*wuh,*wul,*wdh,*wdl;
    u16 *wsgth,*wsgtl,*wsuph,*wsupl,*wsdnh,*wsdnl;
    u16 *x1h,*x1l,*ath,*atl,*x2h,*x2l,*acth,*actl,*sacth,*sactl;
    SYM(wqh,g_wqh); SYM(wql,g_wql); SYM(wkh,g_wkh); SYM(wkl,g_wkl);
    SYM(wvh,g_wvh); SYM(wvl,g_wvl); SYM(woh,g_woh); SYM(wol,g_wol);
    SYM(wgh,g_wgh); SYM(wgl,g_wgl); SYM(wuh,g_wuh); SYM(wul,g_wul);
    SYM(wdh,g_wdh); SYM(wdl,g_wdl);
    SYM(wsgth,g_wsgth); SYM(wsgtl,g_wsgtl); SYM(wsuph,g_wsuph); SYM(wsupl,g_wsupl);
    SYM(wsdnh,g_wsdnh); SYM(wsdnl,g_wsdnl);
    SYM(x1h,g_x1h); SYM(x1l,g_x1l); SYM(ath,g_ath); SYM(atl,g_atl);
    SYM(x2h,g_x2h); SYM(x2l,g_x2l); SYM(acth,g_acth); SYM(actl,g_actl);
    SYM(sacth,g_sacth); SYM(sactl,g_sactl);

    cudaFuncSetAttribute(attn_kernel, cudaFuncAttributeMaxDynamicSharedMemorySize, ATTN_SMEM_BYTES);
    cudaFuncSetAttribute(gemm_mma<0>, cudaFuncAttributeMaxDynamicSharedMemorySize, GEMM_SMEM);
    cudaFuncSetAttribute(gemm_mma<1>, cudaFuncAttributeMaxDynamicSharedMemorySize, GEMM_SMEM);
    cudaFuncSetAttribute(gemm_mma<2>, cudaFuncAttributeMaxDynamicSharedMemorySize, GEMM_SMEM);
    cudaFuncSetAttribute(gemm_mma<3>, cudaFuncAttributeMaxDynamicSharedMemorySize, GEMM_SMEM);

    // ---- weight conversion (transpose + bf16 split) ----
    transpose_split_kernel<<<dim3(QD/32, Hn/32, 1), 256>>>(wq,   wqh,   wql,   Hn,  QD);
    transpose_split_kernel<<<dim3(KD/32, Hn/32, 1), 256>>>(wk,   wkh,   wkl,   Hn,  KD);
    transpose_split_kernel<<<dim3(KD/32, Hn/32, 1), 256>>>(wv,   wvh,   wvl,   Hn,  KD);
    transpose_split_kernel<<<dim3(Hn/32, QD/32, 1), 256>>>(wo,   woh,   wol,   QD,  Hn);
    transpose_split_kernel<<<dim3(Fn/32, Hn/32, En), 256>>>(wg,  wgh,   wgl,   Hn,  Fn);
    transpose_split_kernel<<<dim3(Fn/32, Hn/32, En), 256>>>(wu,  wuh,   wul,   Hn,  Fn);
    transpose_split_kernel<<<dim3(Hn/32, Fn/32, En), 256>>>(wd,  wdh,   wdl,   Fn,  Hn);
    transpose_split_kernel<<<dim3(FSn/32, Hn/32, 1), 256>>>(wsgt, wsgth, wsgtl, Hn,  FSn);
    transpose_split_kernel<<<dim3(FSn/32, Hn/32, 1), 256>>>(wsup, wsuph, wsupl, Hn,  FSn);
    transpose_split_kernel<<<dim3(Hn/32, FSn/32, 1), 256>>>(wsdn, wsdnh, wsdnl, FSn, Hn);

    // ---- attention block ----
    rmsnorm_kernel<<<Tn, 256>>>(hs, ln1, x1p);
    split_kernel<<<2048, 256>>>(x1p, x1h, x1l, Tn*Hn);
    gemm_mma<0><<<dim3(QD/128, Tn/128), 256, GEMM_SMEM>>>(x1h, x1l, wqh, wql, nullptr, qp, Tn, QD, Hn);
    gemm_mma<0><<<dim3(KD/128, Tn/128), 256, GEMM_SMEM>>>(x1h, x1l, wkh, wkl, nullptr, kp, Tn, KD, Hn);
    gemm_mma<0><<<dim3(KD/128, Tn/128), 256, GEMM_SMEM>>>(x1h, x1l, wvh, wvl, nullptr, vp, Tn, KD, Hn);
    rope_kernel<<<dim3(Tn, NHn),  64>>>(qp, pos, NHn);
    rope_kernel<<<dim3(Tn, NKVn), 64>>>(kp, pos, NKVn);
    attn_kernel<<<dim3(Tn/64, NHn), 256, ATTN_SMEM_BYTES>>>(qp, kp, vp, atp);
    split_kernel<<<2048, 256>>>(atp, ath, atl, Tn*QD);
    gemm_mma<1><<<dim3(Hn/128, Tn/128), 256, GEMM_SMEM>>>(ath, atl, woh, wol, hs, hidp, Tn, Hn, QD);

    // ---- MoE block ----
    rmsnorm_kernel<<<Tn, 256>>>(hidp, ln2, x2p);
    split_kernel<<<2048, 256>>>(x2p, x2h, x2l, Tn*Hn);
    router_kernel<<<Tn, 256>>>(x2p, rw);
    sgate_kernel<<<Tn, 128>>>(x2p, wsg);
    build_perm_kernel<<<1, 256>>>();
    gemm_mma<2><<<dim3(Fn/128, 32, En), 256, GEMM_SMEM>>>(x2h, x2l, wgh, wgl, nullptr, gbufp, Tn, Fn, Hn);
    gemm_mma<2><<<dim3(Fn/128, 32, En), 256, GEMM_SMEM>>>(x2h, x2l, wuh, wul, nullptr, ubufp, Tn, Fn, Hn);
    silumul_split_kernel<<<4096, 256>>>(gbufp, ubufp, acth, actl, 2*Tn*Fn);
    gemm_mma<3><<<dim3(Hn/128, 32, En), 256, GEMM_SMEM>>>(acth, actl, wdh, wdl, nullptr, nullptr, Tn, Hn, Fn);

    // ---- shared expert ----
    gemm_mma<0><<<dim3(FSn/128, Tn/128), 256, GEMM_SMEM>>>(x2h, x2l, wsgth, wsgtl, nullptr, sggp, Tn, FSn, Hn);
    gemm_mma<0><<<dim3(FSn/128, Tn/128), 256, GEMM_SMEM>>>(x2h, x2l, wsuph, wsupl, nullptr, sgup, Tn, FSn, Hn);
    silumul_split_kernel<<<4096, 256>>>(sggp, sgup, sacth, sactl, Tn*FSn);
    gemm_mma<0><<<dim3(Hn/128, Tn/128), 256, GEMM_SMEM>>>(sacth, sactl, wsdnh, wsdnl, nullptr, sop, Tn, Hn, FSn);

    combine_kernel<<<16384, 256>>>(hidp, sop, out);
}

// round 16
// speedup vs baseline: 1.2807x; 1.2807x over previous
#include <cuda_runtime.h>
#include <cuda_fp16.h>
#include <math.h>
#include <stdint.h>
typedef unsigned short u16;

#define Tn 2048
#define Hn 2048
#define NHn 16
#define NKVn 4
#define HDn 128
#define En 8
#define Fn 4096
#define FSn 4096
#define QD (NHn*HDn)
#define KD (NKVn*HDn)

// ---------- fp32 scratch ----------
__device__ float g_x1[Tn*Hn];
__device__ float g_q[Tn*QD];
__device__ float g_k[Tn*KD];
__device__ float g_v[Tn*KD];
__device__ float g_attn[Tn*QD];
__device__ float g_hidden[Tn*Hn];
__device__ float g_x2[Tn*Hn];
__device__ float g_gbuf[2*Tn*Fn];
__device__ float g_ubuf[2*Tn*Fn];
__device__ float g_moe[2*Tn*Hn];
__device__ float g_sgg[Tn*FSn];
__device__ float g_sgu[Tn*FSn];
__device__ float g_so[Tn*Hn];
__device__ float g_sgate[Tn];
__device__ int   g_te[Tn*2];
__device__ float g_tw[Tn*2];
__device__ int   g_ptok[2*Tn];
__device__ int   g_pslot[2*Tn];
__device__ float g_pw[2*Tn];
__device__ int   g_cnt[En];
__device__ int   g_off[En];

// ---------- fp16 planes: weights [N][K] hi/lo, activations [M][K] single ----------
__device__ u16 g_wqh[Hn*QD],  g_wql[Hn*QD];
__device__ u16 g_wkh[Hn*KD],  g_wkl[Hn*KD];
__device__ u16 g_wvh[Hn*KD],  g_wvl[Hn*KD];
__device__ u16 g_woh[QD*Hn],  g_wol[QD*Hn];
__device__ u16 g_wgh[(size_t)En*Hn*Fn], g_wgl[(size_t)En*Hn*Fn];
__device__ u16 g_wuh[(size_t)En*Hn*Fn], g_wul[(size_t)En*Hn*Fn];
__device__ u16 g_wdh[(size_t)En*Fn*Hn], g_wdl[(size_t)En*Fn*Hn];
__device__ u16 g_wsgth[Hn*FSn], g_wsgtl[Hn*FSn];
__device__ u16 g_wsuph[Hn*FSn], g_wsupl[Hn*FSn];
__device__ u16 g_wsdnh[FSn*Hn], g_wsdnl[FSn*Hn];
__device__ u16 g_x1h[Tn*Hn];
__device__ u16 g_ath[Tn*QD];
__device__ u16 g_x2h[Tn*Hn];
__device__ u16 g_acth[2*Tn*Fn];
__device__ u16 g_sacth[Tn*FSn];

// ---------- helpers ----------
__device__ __forceinline__ uint32_t smem_u32(const void* p){
    uint32_t a; asm("{ .reg .u64 t; cvta.to.shared.u64 t, %1; cvt.u32.u64 %0, t; }":"=r"(a):"l"(p)); return a;
}
__device__ __forceinline__ void cpa16(uint32_t dst, const void* src){
    asm volatile("cp.async.cg.shared.global [%0], [%1], 16;" :: "r"(dst), "l"(src) : "memory");
}
template<int N> __device__ __forceinline__ void cp_wait(){
    asm volatile("cp.async.wait_group %0;" :: "n"(N) : "memory");
}
__device__ __forceinline__ void ldsm4(uint32_t* r, uint32_t a){
    asm volatile("ldmatrix.sync.aligned.m8n8.x4.shared.b16 {%0,%1,%2,%3}, [%4];"
        : "=r"(r[0]),"=r"(r[1]),"=r"(r[2]),"=r"(r[3]) : "r"(a));
}
__device__ __forceinline__ void mma16816(float* c, const uint32_t* a, uint32_t b0, uint32_t b1){
    asm volatile("mma.sync.aligned.m16n8k16.row.col.f32.f16.f16.f32 "
        "{%0,%1,%2,%3}, {%4,%5,%6,%7}, {%8,%9}, {%0,%1,%2,%3};"
        : "+f"(c[0]),"+f"(c[1]),"+f"(c[2]),"+f"(c[3])
        : "r"(a[0]),"r"(a[1]),"r"(a[2]),"r"(a[3]),"r"(b0),"r"(b1));
}

// smem: 3 planes (A, Bh, Bl) of 128 rows x 32 fp16, row stride 80B (conflict-free ldmatrix)
#define RSB    80
#define PLANE  (128*RSB)       // 10240
#define OF_BH  PLANE
#define OF_BL  (2*PLANE)
#define STAGE  (3*PLANE)       // 30720
#define GEMM_SMEM (2*STAGE)    // 61440

// ---------- converters ----------
// W [K][N] fp32 -> Th/Tl [N][K] fp16 (hi/lo).  Tile 64k x 32n; u32-packed coalesced stores.
__global__ void __launch_bounds__(256) transpose_split_kernel(
    const float* __restrict__ W, u16* __restrict__ Th, u16* __restrict__ Tl, int K, int N)
{
    __shared__ float tile[64][33];
    size_t zo = (size_t)blockIdx.z * K * N;
    W += zo; Th += zo; Tl += zo;
    int nt = blockIdx.x*32, kt = blockIdx.y*64;
    int tx = threadIdx.x & 31, ty = threadIdx.x >> 5;   // ty: 0..7
#pragma unroll
    for (int j = 0; j < 64; j += 8)
        tile[ty+j][tx] = W[(size_t)(kt+ty+j)*N + nt + tx];
    __syncthreads();
#pragma unroll
    for (int q = 0; q < 4; q++) {
        int n = ty + 8*q;
        float v0 = tile[2*tx][n],   v1 = tile[2*tx+1][n];
        __half h0 = __float2half_rn(v0), h1 = __float2half_rn(v1);
        __half l0 = __float2half_rn(v0 - __half2float(h0));
        __half l1 = __float2half_rn(v1 - __half2float(h1));
        uint32_t hv = (uint32_t)__half_as_ushort(h0) | ((uint32_t)__half_as_ushort(h1) << 16);
        uint32_t lv = (uint32_t)__half_as_ushort(l0) | ((uint32_t)__half_as_ushort(l1) << 16);
        size_t o = ((size_t)(nt + n)*K + kt)/2 + tx;
        ((uint32_t*)Th)[o] = hv;
        ((uint32_t*)Tl)[o] = lv;
    }
}
// fp32 -> single fp16 plane
__global__ void split_half_kernel(const float* __restrict__ x, u16* __restrict__ h, int n)
{
    int i = blockIdx.x*blockDim.x + threadIdx.x;
    for (; i < n; i += gridDim.x*blockDim.x)
        h[i] = __half_as_ushort(__float2half_rn(x[i]));
}
__global__ void silumul_half_kernel(const float* __restrict__ g, const float* __restrict__ u,
                                    u16* __restrict__ h, int n)
{
    int i = blockIdx.x*blockDim.x + threadIdx.x;
    for (; i < n; i += gridDim.x*blockDim.x) {
        float gv = g[i];
        float v = gv/(1.f+__expf(-gv))*u[i];
        h[i] = __half_as_ushort(__float2half_rn(v));
    }
}

// ---------- split-fp16 HMMA GEMM ----------
// C = A@B^T, A fp16 single plane [M][K], B fp16 hi/lo [N][K].  2 terms: A*Bh + A*Bl.
// 128x128 tile, BK=32, 8 warps (4m x 2n), warp tile 32x64.
// MODE: 0 plain, 1 +Cadd, 2 gather A rows via g_ptok -> contiguous C, 3 contiguous A -> scatter*weight to g_moe
template<int MODE>
__global__ void __launch_bounds__(256, 2) gemm_mma(
    const u16* __restrict__ Ah_,
    const u16* __restrict__ Bh_, const u16* __restrict__ Bl_,
    const float* __restrict__ Cadd, float* __restrict__ C,
    int M, int N, int K)
{
    int cnt = M, off = 0;
    const u16 *Bh = Bh_, *Bl = Bl_;
    if (MODE >= 2) {
        int e = blockIdx.z;
        cnt = g_cnt[e]; off = g_off[e];
        size_t bo = (size_t)e * K * N;
        Bh += bo; Bl += bo;
    }
    const int bm = blockIdx.y * 128;
    if (bm >= cnt) return;
    const int bn = blockIdx.x * 128;

    extern __shared__ char smc[];
    const uint32_t sb = smem_u32(smc);
    const int tid = threadIdx.x, wid = tid>>5, lane = tid&31;

    // ---- gmem load mapping: thread covers row ar, 16 fp16 at col half*16 per plane ----
    const int ar = tid >> 1, half = tid & 1;
    int grow;
    if (MODE == 2)      { int r = bm+ar; if (r >= cnt) r = cnt-1; grow = g_ptok[off + r]; }
    else if (MODE == 3) { int r = bm+ar; if (r >= cnt) r = cnt-1; grow = off + r; }
    else                  grow = bm + ar;
    const u16* sAh = Ah_ + (size_t)grow*K + half*16;
    const u16* sBh = Bh  + (size_t)(bn+ar)*K + half*16;
    const u16* sBl = Bl  + (size_t)(bn+ar)*K + half*16;
    const uint32_t dA = sb + ar*RSB + half*32;

    // ---- compute-side smem addresses ----
    const int wm = wid & 3, wn = wid >> 2;
    const uint32_t aBase = sb + (uint32_t)(wm*32 + (lane & 15))*RSB + (uint32_t)(lane >> 4)*16;
    const uint32_t bBase = sb + OF_BH
        + (uint32_t)(wn*64 + (lane & 7) + ((lane >> 4) & 1)*8)*RSB
        + (uint32_t)((lane >> 3) & 1)*16;

    float acc[2][8][4];
#pragma unroll
    for (int mt = 0; mt < 2; mt++)
#pragma unroll
        for (int nt = 0; nt < 8; nt++)
#pragma unroll
            for (int j = 0; j < 4; j++) acc[mt][nt][j] = 0.f;

    const int ktiles = K / 32;

#define ISSUE(st, kb) do { \
    uint32_t d_ = dA + (uint32_t)(st)*STAGE; const int ko_ = (kb)*32; \
    cpa16(d_,            sAh + ko_); cpa16(d_ + 16,            sAh + ko_ + 8); \
    cpa16(d_ + OF_BH,    sBh + ko_); cpa16(d_ + OF_BH + 16,    sBh + ko_ + 8); \
    cpa16(d_ + OF_BL,    sBl + ko_); cpa16(d_ + OF_BL + 16,    sBl + ko_ + 8); \
    asm volatile("cp.async.commit_group;" ::: "memory"); } while(0)

    ISSUE(0, 0);
    for (int kb = 0; kb < ktiles; kb++) {
        cp_wait<0>();
        __syncthreads();
        if (kb + 1 < ktiles) ISSUE((kb+1)&1, kb+1);   // overlaps with compute below
        const uint32_t st = (uint32_t)(kb & 1) * STAGE;
#pragma unroll
        for (int ks = 0; ks < 2; ks++) {
            uint32_t ah[2][4];
#pragma unroll
            for (int mt = 0; mt < 2; mt++)
                ldsm4(ah[mt], aBase + st + (uint32_t)mt*16*RSB + (uint32_t)ks*32);
#pragma unroll
            for (int ng = 0; ng < 2; ng++) {
                uint32_t bh[8], bl[8];
                uint32_t b0 = bBase + st + (uint32_t)(ng*32)*RSB + (uint32_t)ks*32;
                uint32_t b1 = b0 + 16*RSB;
                ldsm4(&bh[0], b0);
                ldsm4(&bh[4], b1);
                ldsm4(&bl[0], b0 + PLANE);
                ldsm4(&bl[4], b1 + PLANE);
                // term-major: 8 independent accumulators between reuses
#pragma unroll
                for (int q = 0; q < 4; q++)
#pragma unroll
                    for (int mt = 0; mt < 2; mt++)
                        mma16816(acc[mt][ng*4+q], ah[mt], bh[2*q], bh[2*q+1]);
#pragma unroll
                for (int q = 0; q < 4; q++)
#pragma unroll
                    for (int mt = 0; mt < 2; mt++)
                        mma16816(acc[mt][ng*4+q], ah[mt], bl[2*q], bl[2*q+1]);
            }
        }
    }
#undef ISSUE

    // ---- epilogue ----
    const int gid = lane >> 2, tg = lane & 3;
    const int cb = bn + wn*64 + tg*2;
#pragma unroll
    for (int mt = 0; mt < 2; mt++) {
        const int lr0 = wm*32 + mt*16 + gid;
        const int lr1 = lr0 + 8;
        if (MODE == 3) {
            const bool v0 = (bm + lr0) < cnt, v1 = (bm + lr1) < cnt;
            int p0 = off + bm + lr0, p1 = off + bm + lr1;
            int tok0 = v0 ? g_ptok[p0] : 0, slot0 = v0 ? g_pslot[p0] : 0;
            int tok1 = v1 ? g_ptok[p1] : 0, slot1 = v1 ? g_pslot[p1] : 0;
            float w0 = v0 ? g_pw[p0] : 0.f, w1 = v1 ? g_pw[p1] : 0.f;
            float* d0 = g_moe + (size_t)slot0*Tn*Hn + (size_t)tok0*Hn + cb;
            float* d1 = g_moe + (size_t)slot1*Tn*Hn + (size_t)tok1*Hn + cb;
#pragma unroll
            for (int nt = 0; nt < 8; nt++) {
                if (v0) { float2 o; o.x = acc[mt][nt][0]*w0; o.y = acc[mt][nt][1]*w0; *(float2*)(d0 + nt*8) = o; }
                if (v1) { float2 o; o.x = acc[mt][nt][2]*w1; o.y = acc[mt][nt][3]*w1; *(float2*)(d1 + nt*8) = o; }
            }
        } else if (MODE == 2) {
            const bool v0 = (bm + lr0) < cnt, v1 = (bm + lr1) < cnt;
            float* d0 = C + (size_t)(off + bm + lr0)*N + cb;
            float* d1 = C + (size_t)(off + bm + lr1)*N + cb;
#pragma unroll
            for (int nt = 0; nt < 8; nt++) {
                if (v0) { float2 o; o.x = acc[mt][nt][0]; o.y = acc[mt][nt][1]; *(float2*)(d0 + nt*8) = o; }
                if (v1) { float2 o; o.x = acc[mt][nt][2]; o.y = acc[mt][nt][3]; *(float2*)(d1 + nt*8) = o; }
            }
        } else {
            float* d0 = C + (size_t)(bm + lr0)*N + cb;
            float* d1 = C + (size_t)(bm + lr1)*N + cb;
            if (MODE == 1) {
                const float* a0 = Cadd + (size_t)(bm + lr0)*N + cb;
                const float* a1 = Cadd + (size_t)(bm + lr1)*N + cb;
#pragma unroll
                for (int nt = 0; nt < 8; nt++) {
                    float2 r0 = *(const float2*)(a0 + nt*8);
                    float2 r1 = *(const float2*)(a1 + nt*8);
                    float2 o0; o0.x = acc[mt][nt][0] + r0.x; o0.y = acc[mt][nt][1] + r0.y;
                    float2 o1; o1.x = acc[mt][nt][2] + r1.x; o1.y = acc[mt][nt][3] + r1.y;
                    *(float2*)(d0 + nt*8) = o0;
                    *(float2*)(d1 + nt*8) = o1;
                }
            } else {
#pragma unroll
                for (int nt = 0; nt < 8; nt++) {
                    float2 o0; o0.x = acc[mt][nt][0]; o0.y = acc[mt][nt][1];
                    float2 o1; o1.x = acc[mt][nt][2]; o1.y = acc[mt][nt][3];
                    *(float2*)(d0 + nt*8) = o0;
                    *(float2*)(d1 + nt*8) = o1;
                }
            }
        }
    }
}

// ---------- non-GEMM kernels (unchanged, passing) ----------
__global__ void __launch_bounds__(256) rmsnorm_kernel(
    const float* __restrict__ x, const float* __restrict__ w, float* __restrict__ y)
{
    int t = blockIdx.x, tid = threadIdx.x;
    __shared__ float red[256]; __shared__ float rs;
    const float* xr = x + (size_t)t*Hn;
    float s = 0.f;
    for (int j = tid; j < Hn; j += 256) { float v = xr[j]; s += v*v; }
    red[tid] = s; __syncthreads();
    for (int o = 128; o > 0; o >>= 1) { if (tid < o) red[tid] += red[tid+o]; __syncthreads(); }
    if (tid == 0) rs = rsqrtf(red[0]/(float)Hn + 1e-6f);
    __syncthreads();
    float* yr = y + (size_t)t*Hn;
    for (int j = tid; j < Hn; j += 256) yr[j] = xr[j]*rs*w[j];
}

__global__ void rope_kernel(float* __restrict__ x, const int* __restrict__ pos, int nheads)
{
    int t = blockIdx.x, h = blockIdx.y, i = threadIdx.x;
    float* p = x + ((size_t)t*nheads + h)*HDn;
    float inv = powf(1.0e6f, -((float)i)/64.0f);
    float ang = (float)pos[t] * inv;
    float sv, cv; sincosf(ang, &sv, &cv);
    float a = p[i], b = p[i+64];
    p[i] = a*cv - b*sv;  p[i+64] = b*cv + a*sv;
}

#define ATTN_SMEM_BYTES ((64*132*2 + 64*65 + 192) * 4)
__global__ void __launch_bounds__(256) attn_kernel(
    const float* __restrict__ q, const float* __restrict__ k,
    const float* __restrict__ v, float* __restrict__ out)
{
    extern __shared__ float sm[];
    float* Qs  = sm;
    float* KVs = sm + 64*132;
    float* Ps  = sm + 2*64*132;
    float* m_s = Ps + 64*65;
    float* l_s = m_s + 64;
    float* al_s = l_s + 64;
    const int tid = threadIdx.x;
    const int m0 = blockIdx.x * 64;
    const int h  = blockIdx.y;
    const int kvh = h / (NHn/NKVn);
    const float scale = 0.08838834764831845f;
    {
        int r = tid >> 2, c = (tid & 3) * 32;
        const float* src = q + ((size_t)(m0 + r)*NHn + h)*HDn + c;
        float* dst = Qs + r*132 + c;
#pragma unroll
        for (int j = 0; j < 32; j += 4) *(float4*)(dst + j) = *(const float4*)(src + j);
    }
    if (tid < 64) { m_s[tid] = -INFINITY; l_s[tid] = 0.f; }
    const int tx = tid & 15, ty = tid >> 4;
    const int r0 = ty*4, sc0 = tx*4, oc0 = tx*8;
    float acc[4][8];
#pragma unroll
    for (int i = 0; i < 4; i++)
#pragma unroll
        for (int j = 0; j < 8; j++) acc[i][j] = 0.f;
    const int ntiles = m0/64 + 1;
    for (int t = 0; t < ntiles; ++t) {
        const int s0 = t*64;
        __syncthreads();
        {
            int r = tid >> 2, c = (tid & 3)*32;
            const float* src = k + ((size_t)(s0 + r)*NKVn + kvh)*HDn + c;
            float* dst = KVs + r*132 + c;
#pragma unroll
            for (int j = 0; j < 32; j += 4) *(float4*)(dst + j) = *(const float4*)(src + j);
        }
        __syncthreads();
        float s4[4][4];
#pragma unroll
        for (int i = 0; i < 4; i++)
#pragma unroll
            for (int j = 0; j < 4; j++) s4[i][j] = 0.f;
#pragma unroll 4
        for (int kk = 0; kk < HDn; kk += 4) {
            float4 a[4], b[4];
#pragma unroll
            for (int i = 0; i < 4; i++) a[i] = *(const float4*)(Qs + (r0+i)*132 + kk);
#pragma unroll
            for (int j = 0; j < 4; j++) b[j] = *(const float4*)(KVs + (sc0+j)*132 + kk);
#pragma unroll
            for (int i = 0; i < 4; i++)
#pragma unroll
                for (int j = 0; j < 4; j++)
                    s4[i][j] += a[i].x*b[j].x + a[i].y*b[j].y + a[i].z*b[j].z + a[i].w*b[j].w;
        }
#pragma unroll
        for (int i = 0; i < 4; i++)
#pragma unroll
            for (int j = 0; j < 4; j++) {
                float vv = s4[i][j]*scale;
                if (s0 + sc0 + j > m0 + r0 + i) vv = -1e30f;
                Ps[(r0+i)*65 + sc0 + j] = vv;
            }
        __syncthreads();
        {
            int r = tid >> 2, sub = tid & 3;
            float* prow = Ps + r*65 + sub*16;
            float mx = -INFINITY;
#pragma unroll
            for (int j2 = 0; j2 < 16; j2++) mx = fmaxf(mx, prow[j2]);
#pragma unroll
            for (int o = 1; o < 4; o <<= 1) mx = fmaxf(mx, __shfl_xor_sync(0xffffffffu, mx, o));
            float mprev = m_s[r];
            float mnew  = fmaxf(mprev, mx);
            float sum = 0.f;
#pragma unroll
            for (int j2 = 0; j2 < 16; j2++) { float p = __expf(prow[j2]-mnew); prow[j2] = p; sum += p; }
#pragma unroll
            for (int o = 1; o < 4; o <<= 1) sum += __shfl_xor_sync(0xffffffffu, sum, o);
            if (sub == 0) {
                float al = __expf(mprev - mnew);
                al_s[r] = al;  l_s[r] = l_s[r]*al + sum;  m_s[r] = mnew;
            }
        }
        __syncthreads();
        {
            int r = tid >> 2, c = (tid & 3)*32;
            const float* src = v + ((size_t)(s0 + r)*NKVn + kvh)*HDn + c;
            float* dst = KVs + r*132 + c;
#pragma unroll
            for (int j = 0; j < 32; j += 4) *(float4*)(dst + j) = *(const float4*)(src + j);
        }
        __syncthreads();
        {
#pragma unroll
            for (int i = 0; i < 4; i++) {
                float al = al_s[r0+i];
#pragma unroll
                for (int j = 0; j < 8; j++) acc[i][j] *= al;
            }
#pragma unroll 4
            for (int s = 0; s < 64; s++) {
                float4 v0 = *(const float4*)(KVs + s*132 + oc0);
                float4 v1 = *(const float4*)(KVs + s*132 + oc0 + 4);
                float p[4];
#pragma unroll
                for (int i = 0; i < 4; i++) p[i] = Ps[(r0+i)*65 + s];
#pragma unroll
                for (int i = 0; i < 4; i++) {
                    acc[i][0]=fmaf(p[i],v0.x,acc[i][0]); acc[i][1]=fmaf(p[i],v0.y,acc[i][1]);
                    acc[i][2]=fmaf(p[i],v0.z,acc[i][2]); acc[i][3]=fmaf(p[i],v0.w,acc[i][3]);
                    acc[i][4]=fmaf(p[i],v1.x,acc[i][4]); acc[i][5]=fmaf(p[i],v1.y,acc[i][5]);
                    acc[i][6]=fmaf(p[i],v1.z,acc[i][6]); acc[i][7]=fmaf(p[i],v1.w,acc[i][7]);
                }
            }
        }
    }
    __syncthreads();
#pragma unroll
    for (int i = 0; i < 4; i++) {
        float inv = 1.f / l_s[r0+i];
        float* dst = out + ((size_t)(m0 + r0 + i)*NHn + h)*HDn + oc0;
#pragma unroll
        for (int j = 0; j < 8; j++) dst[j] = acc[i][j]*inv;
    }
}

__global__ void __launch_bounds__(256) router_kernel(
    const float* __restrict__ x, const float* __restrict__ rw)
{
    int t = blockIdx.x;
    int w = threadIdx.x >> 5, lane = threadIdx.x & 31;
    __shared__ float lg[En];
    const float* xr = x + (size_t)t*Hn;
    float s = 0.f;
    for (int j = lane; j < Hn; j += 32) s += xr[j]*rw[(size_t)j*En + w];
#pragma unroll
    for (int o = 16; o > 0; o >>= 1) s += __shfl_xor_sync(0xffffffffu, s, o);
    if (lane == 0) lg[w] = s;
    __syncthreads();
    if (threadIdx.x == 0) {
        float mx = lg[0];
        for (int e = 1; e < En; e++) mx = fmaxf(mx, lg[e]);
        float p[En]; float sum = 0.f;
        for (int e = 0; e < En; e++) { p[e] = expf(lg[e]-mx); sum += p[e]; }
        for (int e = 0; e < En; e++) p[e] /= sum;
        int e0 = 0;
        for (int e = 1; e < En; e++) if (p[e] > p[e0]) e0 = e;
        int e1 = (e0 == 0) ? 1 : 0;
        for (int e = 0; e < En; e++) if (e != e0 && p[e] > p[e1]) e1 = e;
        float inv = 1.f/(p[e0]+p[e1]);
        g_te[t*2] = e0; g_te[t*2+1] = e1;
        g_tw[t*2] = p[e0]*inv; g_tw[t*2+1] = p[e1]*inv;
    }
}

__global__ void __launch_bounds__(128) sgate_kernel(
    const float* __restrict__ x, const float* __restrict__ wsg)
{
    int t = blockIdx.x, tid = threadIdx.x;
    __shared__ float red[128];
    const float* xr = x + (size_t)t*Hn;
    float s = 0.f;
    for (int j = tid; j < Hn; j += 128) s += xr[j]*wsg[j];
    red[tid] = s; __syncthreads();
    for (int o = 64; o > 0; o >>= 1) { if (tid < o) red[tid] += red[tid+o]; __syncthreads(); }
    if (tid == 0) g_sgate[t] = 1.f/(1.f + expf(-red[0]));
}

__global__ void __launch_bounds__(256) build_perm_kernel()
{
    __shared__ int cnt_s[En], off_s[En], cur[En];
    int tid = threadIdx.x;
    if (tid < En) cnt_s[tid] = 0;
    __syncthreads();
    for (int t = tid; t < Tn; t += 256) {
        atomicAdd(&cnt_s[g_te[t*2]], 1);
        atomicAdd(&cnt_s[g_te[t*2+1]], 1);
    }
    __syncthreads();
    if (tid == 0) { int o = 0; for (int e = 0; e < En; e++) { off_s[e] = o; o += cnt_s[e]; } }
    __syncthreads();
    if (tid < En) cur[tid] = off_s[tid];
    __syncthreads();
    for (int t = tid; t < Tn; t += 256) {
        for (int s = 0; s < 2; s++) {
            int e = g_te[t*2+s];
            int p = atomicAdd(&cur[e], 1);
            g_ptok[p] = t; g_pslot[p] = s; g_pw[p] = g_tw[t*2+s];
        }
    }
    __syncthreads();
    if (tid < En) { g_cnt[tid] = cnt_s[tid]; g_off[tid] = off_s[tid]; }
}

__global__ void combine_kernel(const float* __restrict__ hidden, const float* __restrict__ so,
                               float* __restrict__ out)
{
    const int total = Tn*Hn;
    int i = blockIdx.x*blockDim.x + threadIdx.x;
    for (; i < total; i += gridDim.x*blockDim.x) {
        int t = i / Hn;
        out[i] = hidden[i] + g_moe[i] + g_moe[total + i] + g_sgate[t]*so[i];
    }
}

// ---------- launch ----------
#define SYM(p, s) cudaGetSymbolAddress((void**)&p, s)
extern "C" void kernel_launch(void* const* d_in, const int* in_sizes, int n_in,
                              void* d_out, int out_size)
{
    (void)in_sizes; (void)n_in; (void)out_size;
    const float* hs   = (const float*)d_in[0];
    const int*   pos  = (const int*)  d_in[1];
    const float* ln1  = (const float*)d_in[2];
    const float* ln2  = (const float*)d_in[3];
    const float* wq   = (const float*)d_in[4];
    const float* wk   = (const float*)d_in[5];
    const float* wv   = (const float*)d_in[6];
    const float* wo   = (const float*)d_in[7];
    const float* rw   = (const float*)d_in[8];
    const float* wg   = (const float*)d_in[9];
    const float* wu   = (const float*)d_in[10];
    const float* wd   = (const float*)d_in[11];
    const float* wsgt = (const float*)d_in[12];
    const float* wsup = (const float*)d_in[13];
    const float* wsdn = (const float*)d_in[14];
    const float* wsg  = (const float*)d_in[15];
    float* out = (float*)d_out;

    float *x1p,*qp,*kp,*vp,*atp,*hidp,*x2p,*gbufp,*ubufp,*sggp,*sgup,*sop;
    SYM(x1p,g_x1); SYM(qp,g_q); SYM(kp,g_k); SYM(vp,g_v); SYM(atp,g_attn);
    SYM(hidp,g_hidden); SYM(x2p,g_x2); SYM(gbufp,g_gbuf); SYM(ubufp,g_ubuf);
    SYM(sggp,g_sgg); SYM(sgup,g_sgu); SYM(sop,g_so);

    u16 *wqh,*wql,*wkh,*wkl,*wvh,*wvl,*woh,*wol,*wgh,*wgl,*wuh,*wul,*wdh,*wdl;
    u16 *wsgth,*wsgtl,*wsuph,*wsupl,*wsdnh,*wsdnl;
    u16 *x1h,*ath,*x2h,*acth,*sacth;
    SYM(wqh,g_wqh); SYM(wql,g_wql); SYM(wkh,g_wkh); SYM(wkl,g_wkl);
    SYM(wvh,g_wvh); SYM(wvl,g_wvl); SYM(woh,g_woh); SYM(wol,g_wol);
    SYM(wgh,g_wgh); SYM(wgl,g_wgl); SYM(wuh,g_wuh); SYM(wul,g_wul);
    SYM(wdh,g_wdh); SYM(wdl,g_wdl);
    SYM(wsgth,g_wsgth); SYM(wsgtl,g_wsgtl); SYM(wsuph,g_wsuph); SYM(wsupl,g_wsupl);
    SYM(wsdnh,g_wsdnh); SYM(wsdnl,g_wsdnl);
    SYM(x1h,g_x1h); SYM(ath,g_ath); SYM(x2h,g_x2h); SYM(acth,g_acth); SYM(sacth,g_sacth);

    cudaFuncSetAttribute(attn_kernel, cudaFuncAttributeMaxDynamicSharedMemorySize, ATTN_SMEM_BYTES);
    cudaFuncSetAttribute(gemm_mma<0>, cudaFuncAttributeMaxDynamicSharedMemorySize, GEMM_SMEM);
    cudaFuncSetAttribute(gemm_mma<1>, cudaFuncAttributeMaxDynamicSharedMemorySize, GEMM_SMEM);
    cudaFuncSetAttribute(gemm_mma<2>, cudaFuncAttributeMaxDynamicSharedMemorySize, GEMM_SMEM);
    cudaFuncSetAttribute(gemm_mma<3>, cudaFuncAttributeMaxDynamicSharedMemorySize, GEMM_SMEM);

    // ---- weight conversion (transpose + fp16 hi/lo split) ----
    transpose_split_kernel<<<dim3(QD/32,  Hn/64,  1), 256>>>(wq,   wqh,   wql,   Hn,  QD);
    transpose_split_kernel<<<dim3(KD/32,  Hn/64,  1), 256>>>(wk,   wkh,   wkl,   Hn,  KD);
    transpose_split_kernel<<<dim3(KD/32,  Hn/64,  1), 256>>>(wv,   wvh,   wvl,   Hn,  KD);
    transpose_split_kernel<<<dim3(Hn/32,  QD/64,  1), 256>>>(wo,   woh,   wol,   QD,  Hn);
    transpose_split_kernel<<<dim3(Fn/32,  Hn/64,  En), 256>>>(wg,  wgh,   wgl,   Hn,  Fn);
    transpose_split_kernel<<<dim3(Fn/32,  Hn/64,  En), 256>>>(wu,  wuh,   wul,   Hn,  Fn);
    transpose_split_kernel<<<dim3(Hn/32,  Fn/64,  En), 256>>>(wd,  wdh,   wdl,   Fn,  Hn);
    transpose_split_kernel<<<dim3(FSn/32, Hn/64,  1), 256>>>(wsgt, wsgth, wsgtl, Hn,  FSn);
    transpose_split_kernel<<<dim3(FSn/32, Hn/64,  1), 256>>>(wsup, wsuph, wsupl, Hn,  FSn);
    transpose_split_kernel<<<dim3(Hn/32,  FSn/64, 1), 256>>>(wsdn, wsdnh, wsdnl, FSn, Hn);

    // ---- attention block ----
    rmsnorm_kernel<<<Tn, 256>>>(hs, ln1, x1p);
    split_half_kernel<<<2048, 256>>>(x1p, x1h, Tn*Hn);
    gemm_mma<0><<<dim3(QD/128, Tn/128), 256, GEMM_SMEM>>>(x1h, wqh, wql, nullptr, qp, Tn, QD, Hn);
    gemm_mma<0><<<dim3(KD/128, Tn/128), 256, GEMM_SMEM>>>(x1h, wkh, wkl, nullptr, kp, Tn, KD, Hn);
    gemm_mma<0><<<dim3(KD/128, Tn/128), 256, GEMM_SMEM>>>(x1h, wvh, wvl, nullptr, vp, Tn, KD, Hn);
    rope_kernel<<<dim3(Tn, NHn),  64>>>(qp, pos, NHn);
    rope_kernel<<<dim3(Tn, NKVn), 64>>>(kp, pos, NKVn);
    attn_kernel<<<dim3(Tn/64, NHn), 256, ATTN_SMEM_BYTES>>>(qp, kp, vp, atp);
    split_half_kernel<<<2048, 256>>>(atp, ath, Tn*QD);
    gemm_mma<1><<<dim3(Hn/128, Tn/128), 256, GEMM_SMEM>>>(ath, woh, wol, hs, hidp, Tn, Hn, QD);

    // ---- MoE block ----
    rmsnorm_kernel<<<Tn, 256>>>(hidp, ln2, x2p);
    split_half_kernel<<<2048, 256>>>(x2p, x2h, Tn*Hn);
    router_kernel<<<Tn, 256>>>(x2p, rw);
    sgate_kernel<<<Tn, 128>>>(x2p, wsg);
    build_perm_kernel<<<1, 256>>>();
    gemm_mma<2><<<dim3(Fn/128, 32, En), 256, GEMM_SMEM>>>(x2h, wgh, wgl, nullptr, gbufp, Tn, Fn, Hn);
    gemm_mma<2><<<dim3(Fn/128, 32, En), 256, GEMM_SMEM>>>(x2h, wuh, wul, nullptr, ubufp, Tn, Fn, Hn);
    silumul_half_kernel<<<4096, 256>>>(gbufp, ubufp, acth, 2*Tn*Fn);
    gemm_mma<3><<<dim3(Hn/128, 32, En), 256, GEMM_SMEM>>>(acth, wdh, wdl, nullptr, nullptr, Tn, Hn, Fn);

    // ---- shared expert ----
    gemm_mma<0><<<dim3(FSn/128, Tn/128), 256, GEMM_SMEM>>>(x2h, wsgth, wsgtl, nullptr, sggp, Tn, FSn, Hn);
    gemm_mma<0><<<dim3(FSn/128, Tn/128), 256, GEMM_SMEM>>>(x2h, wsuph, wsupl, nullptr, sgup, Tn, FSn, Hn);
    silumul_half_kernel<<<4096, 256>>>(sggp, sgup, sacth, Tn*FSn);
    gemm_mma<0><<<dim3(Hn/128, Tn/128), 256, GEMM_SMEM>>>(sacth, wsdnh, wsdnl, nullptr, sop, Tn, Hn, FSn);

    combine_kernel<<<16384, 256>>>(hidp, sop, out);
}